// round 2
// baseline (speedup 1.0000x reference)
#include <cuda_runtime.h>

#define N_NODES 50000
#define N_EDGES 800000
#define GNN_HID 64

// ---------------- scratch (device globals; no runtime allocation) -------------
__device__ float g_deg[N_NODES];
__device__ float g_dinv[N_NODES];
__device__ int   g_count[N_NODES];
__device__ int   g_off[N_NODES + 1];
__device__ int   g_fill[N_NODES];
__device__ int   g_elist[N_EDGES];
__device__ float g_h1[(size_t)N_NODES * GNN_HID];
__device__ float g_s[N_NODES];
__device__ float g_sagg[N_NODES];
__device__ float g_v[64];     // gcn2_W @ w_gnn
__device__ float g_u[512];    // fc2_W  @ w_mlp
__device__ float g_cconst;    // fcf_b + fc2_b.w_mlp + gcn2_b.w_gnn

// ---------------- tiny precompute: collapse trailing GEMMs --------------------
__global__ void precompute_kernel(const float* __restrict__ g2W, const float* __restrict__ g2b,
                                  const float* __restrict__ f2W, const float* __restrict__ f2b,
                                  const float* __restrict__ ffW, const float* __restrict__ ffb) {
    int tid = threadIdx.x;
    if (tid < 512) {
        float acc = 0.f;
        #pragma unroll 8
        for (int c = 0; c < 64; c++) acc += f2W[tid * 64 + c] * ffW[c];
        g_u[tid] = acc;
    }
    if (tid < 64) {
        float acc = 0.f;
        #pragma unroll 8
        for (int c = 0; c < 64; c++) acc += g2W[tid * 64 + c] * ffW[64 + c];
        g_v[tid] = acc;
    }
    if (tid == 0) {
        float acc = ffb[0];
        for (int c = 0; c < 64; c++) acc += f2b[c] * ffW[c] + g2b[c] * ffW[64 + c];
        g_cconst = acc;
    }
}

__global__ void init_kernel() {
    int i = blockIdx.x * blockDim.x + threadIdx.x;
    if (i < N_NODES) { g_deg[i] = 1.0f; g_count[i] = 0; }
}

__global__ void edge_prep_kernel(const int* __restrict__ ei, const float* __restrict__ ea) {
    int e = blockIdx.x * blockDim.x + threadIdx.x;
    if (e < N_EDGES) {
        int dst = ei[N_EDGES + e];
        atomicAdd(&g_deg[dst], ea[e]);
        atomicAdd(&g_count[dst], 1);
    }
}

__global__ void dinv_kernel() {
    int i = blockIdx.x * blockDim.x + threadIdx.x;
    if (i < N_NODES) g_dinv[i] = rsqrtf(g_deg[i]);   // deg >= 1 always (self loop)
}

// single-block exclusive scan of g_count -> g_off (and seed g_fill)
__global__ void scan_kernel() {
    __shared__ int warp_sums[32];
    int tid = threadIdx.x, lane = tid & 31, wid = tid >> 5;
    int carry = 0;
    for (int base = 0; base < N_NODES; base += 1024) {
        int i = base + tid;
        int v = (i < N_NODES) ? g_count[i] : 0;
        int x = v;
        #pragma unroll
        for (int o = 1; o < 32; o <<= 1) {
            int y = __shfl_up_sync(0xffffffffu, x, o);
            if (lane >= o) x += y;
        }
        if (lane == 31) warp_sums[wid] = x;
        __syncthreads();
        if (wid == 0) {
            int t = warp_sums[lane];
            #pragma unroll
            for (int o = 1; o < 32; o <<= 1) {
                int y = __shfl_up_sync(0xffffffffu, t, o);
                if (lane >= o) t += y;
            }
            warp_sums[lane] = t;
        }
        __syncthreads();
        int warp_prefix = (wid == 0) ? 0 : warp_sums[wid - 1];
        int excl = carry + warp_prefix + x - v;
        if (i < N_NODES) { g_off[i] = excl; g_fill[i] = excl; }
        carry += warp_sums[31];
        __syncthreads();
    }
    if (tid == 0) g_off[N_NODES] = carry;
}

__global__ void fill_kernel(const int* __restrict__ ei) {
    int e = blockIdx.x * blockDim.x + threadIdx.x;
    if (e < N_EDGES) {
        int dst = ei[N_EDGES + e];
        int pos = atomicAdd(&g_fill[dst], 1);
        g_elist[pos] = e;
    }
}

// ---------------- GEMM 1: h1 = x @ gcn1_W   [50000,256]x[256,64] --------------
// BM=32, BN=64, BK=16, 128 threads (16x8), 4x4 register tile (strided).
__global__ __launch_bounds__(128) void gemm1_kernel(const float* __restrict__ x,
                                                    const float* __restrict__ W1) {
    __shared__ float xs[32 * 257];
    __shared__ float ws[16 * 64];
    int tx = threadIdx.x, ty = threadIdx.y;
    int tid = ty * 16 + tx;
    int row0 = blockIdx.x * 32;

    #pragma unroll
    for (int p = 0; p < 16; p++) {
        int q = tid + 128 * p;
        int r = q >> 6, c4 = q & 63;
        float4 v = make_float4(0.f, 0.f, 0.f, 0.f);
        if (row0 + r < N_NODES)
            v = *reinterpret_cast<const float4*>(x + (size_t)(row0 + r) * 256 + c4 * 4);
        xs[r * 257 + c4 * 4 + 0] = v.x;
        xs[r * 257 + c4 * 4 + 1] = v.y;
        xs[r * 257 + c4 * 4 + 2] = v.z;
        xs[r * 257 + c4 * 4 + 3] = v.w;
    }

    float acc[4][4] = {};
    for (int kb = 0; kb < 256; kb += 16) {
        #pragma unroll
        for (int p = 0; p < 2; p++) {
            int q = tid + 128 * p;
            int kk = q >> 4, c4 = q & 15;
            *reinterpret_cast<float4*>(&ws[kk * 64 + c4 * 4]) =
                *reinterpret_cast<const float4*>(W1 + (size_t)(kb + kk) * 64 + c4 * 4);
        }
        __syncthreads();
        #pragma unroll
        for (int kk = 0; kk < 16; kk++) {
            float a[4], b[4];
            #pragma unroll
            for (int i = 0; i < 4; i++) a[i] = xs[(ty + 8 * i) * 257 + kb + kk];
            #pragma unroll
            for (int j = 0; j < 4; j++) b[j] = ws[kk * 64 + tx + 16 * j];
            #pragma unroll
            for (int i = 0; i < 4; i++)
                #pragma unroll
                for (int j = 0; j < 4; j++) acc[i][j] += a[i] * b[j];
        }
        __syncthreads();
    }
    #pragma unroll
    for (int i = 0; i < 4; i++) {
        int row = row0 + ty + 8 * i;
        if (row < N_NODES) {
            #pragma unroll
            for (int j = 0; j < 4; j++)
                g_h1[(size_t)row * 64 + tx + 16 * j] = acc[i][j];
        }
    }
}

// ---------------- fused: CSR gather + self-loop + bias + relu + dot(v) --------
__global__ void gather1_kernel(const int* __restrict__ ei, const float* __restrict__ ea,
                               const float* __restrict__ b1) {
    int gtid = blockIdx.x * blockDim.x + threadIdx.x;
    int node = gtid >> 5;
    int lane = gtid & 31;
    if (node >= N_NODES) return;
    float dinvi = g_dinv[node];
    float d2 = dinvi * dinvi;
    const float* h1n = g_h1 + (size_t)node * 64;
    float acc0 = h1n[lane] * d2;
    float acc1 = h1n[lane + 32] * d2;
    int beg = g_off[node], end = g_off[node + 1];
    for (int j = beg; j < end; j++) {
        int e = g_elist[j];
        int src = ei[e];
        float norm = ea[e] * g_dinv[src] * dinvi;
        const float* h1s = g_h1 + (size_t)src * 64;
        acc0 += h1s[lane] * norm;
        acc1 += h1s[lane + 32] * norm;
    }
    float gg0 = fmaxf(acc0 + b1[lane], 0.f);
    float gg1 = fmaxf(acc1 + b1[lane + 32], 0.f);
    float p = gg0 * g_v[lane] + gg1 * g_v[lane + 32];
    #pragma unroll
    for (int o = 16; o > 0; o >>= 1) p += __shfl_xor_sync(0xffffffffu, p, o);
    if (lane == 0) { g_s[node] = p; g_sagg[node] = d2 * p; }
}

// ---------------- scalar layer-2 aggregation ----------------------------------
__global__ void gather2_kernel(const int* __restrict__ ei, const float* __restrict__ ea) {
    int i = blockIdx.x * blockDim.x + threadIdx.x;
    if (i >= N_NODES) return;
    float dinvi = g_dinv[i];
    float acc = g_sagg[i];  // dinv^2 * s[i] (self loop), written by gather1
    int beg = g_off[i], end = g_off[i + 1];
    for (int j = beg; j < end; j++) {
        int e = g_elist[j];
        int src = ei[e];
        acc += ea[e] * g_dinv[src] * dinvi * g_s[src];
    }
    g_sagg[i] = acc;
}

// ---------------- fused MLP: out = relu(uf@fc1_W + b1).u + sagg + const -------
// BM=32, BN=128 (x4 chunks), BK=16, 128 threads (16x8), 4x8 register tile.
__global__ __launch_bounds__(128) void mlp_final_kernel(const float* __restrict__ uf,
                                                        const float* __restrict__ W1,
                                                        const float* __restrict__ b1,
                                                        float* __restrict__ out) {
    __shared__ float us[32 * 257];
    __shared__ float ws[16 * 128];
    __shared__ float red[32 * 16];
    int tx = threadIdx.x, ty = threadIdx.y;
    int tid = ty * 16 + tx;
    int row0 = blockIdx.x * 32;

    #pragma unroll
    for (int p = 0; p < 16; p++) {
        int q = tid + 128 * p;
        int r = q >> 6, c4 = q & 63;
        float4 v = make_float4(0.f, 0.f, 0.f, 0.f);
        if (row0 + r < N_NODES)
            v = *reinterpret_cast<const float4*>(uf + (size_t)(row0 + r) * 256 + c4 * 4);
        us[r * 257 + c4 * 4 + 0] = v.x;
        us[r * 257 + c4 * 4 + 1] = v.y;
        us[r * 257 + c4 * 4 + 2] = v.z;
        us[r * 257 + c4 * 4 + 3] = v.w;
    }

    float part[4] = {0.f, 0.f, 0.f, 0.f};
    for (int cc = 0; cc < 512; cc += 128) {
        float acc[4][8] = {};
        for (int kb = 0; kb < 256; kb += 16) {
            #pragma unroll
            for (int p = 0; p < 4; p++) {
                int q = tid + 128 * p;
                int kk = q >> 5, c4 = q & 31;
                *reinterpret_cast<float4*>(&ws[kk * 128 + c4 * 4]) =
                    *reinterpret_cast<const float4*>(W1 + (size_t)(kb + kk) * 512 + cc + c4 * 4);
            }
            __syncthreads();
            #pragma unroll
            for (int kk = 0; kk < 16; kk++) {
                float a[4], b[8];
                #pragma unroll
                for (int i = 0; i < 4; i++) a[i] = us[(ty + 8 * i) * 257 + kb + kk];
                #pragma unroll
                for (int j = 0; j < 8; j++) b[j] = ws[kk * 128 + tx + 16 * j];
                #pragma unroll
                for (int i = 0; i < 4; i++)
                    #pragma unroll
                    for (int j = 0; j < 8; j++) acc[i][j] += a[i] * b[j];
            }
            __syncthreads();
        }
        // epilogue for this column chunk: relu + dot with u
        #pragma unroll
        for (int j = 0; j < 8; j++) {
            int c = cc + tx + 16 * j;
            float bb = b1[c];
            float uu = g_u[c];
            #pragma unroll
            for (int i = 0; i < 4; i++) {
                float h = acc[i][j] + bb;
                if (h > 0.f) part[i] += h * uu;
            }
        }
    }
    #pragma unroll
    for (int i = 0; i < 4; i++) red[(ty + 8 * i) * 16 + tx] = part[i];
    __syncthreads();
    if (tid < 32) {
        float sum = 0.f;
        #pragma unroll
        for (int t = 0; t < 16; t++) sum += red[tid * 16 + t];
        int row = row0 + tid;
        if (row < N_NODES) out[row] = sum + g_sagg[row] + g_cconst;
    }
}

// ------------------------------------------------------------------------------
extern "C" void kernel_launch(void* const* d_in, const int* in_sizes, int n_in,
                              void* d_out, int out_size) {
    const float* x   = (const float*)d_in[0];
    const int*   ei  = (const int*)d_in[1];
    const float* ea  = (const float*)d_in[2];
    const float* uf  = (const float*)d_in[3];
    const float* g1W = (const float*)d_in[4];
    const float* g1b = (const float*)d_in[5];
    const float* g2W = (const float*)d_in[6];
    const float* g2b = (const float*)d_in[7];
    const float* f1W = (const float*)d_in[8];
    const float* f1b = (const float*)d_in[9];
    const float* f2W = (const float*)d_in[10];
    const float* f2b = (const float*)d_in[11];
    const float* ffW = (const float*)d_in[12];
    const float* ffb = (const float*)d_in[13];
    float* out = (float*)d_out;

    precompute_kernel<<<1, 512>>>(g2W, g2b, f2W, f2b, ffW, ffb);
    init_kernel<<<(N_NODES + 255) / 256, 256>>>();
    edge_prep_kernel<<<(N_EDGES + 255) / 256, 256>>>(ei, ea);
    dinv_kernel<<<(N_NODES + 255) / 256, 256>>>();
    scan_kernel<<<1, 1024>>>();
    fill_kernel<<<(N_EDGES + 255) / 256, 256>>>(ei);
    gemm1_kernel<<<(N_NODES + 31) / 32, dim3(16, 8)>>>(x, g1W);
    gather1_kernel<<<((size_t)N_NODES * 32 + 255) / 256, 256>>>(ei, ea, g1b);
    gather2_kernel<<<(N_NODES + 255) / 256, 256>>>(ei, ea);
    mlp_final_kernel<<<(N_NODES + 31) / 32, dim3(16, 8)>>>(uf, f1W, f1b, out);
}

// round 7
// speedup vs baseline: 1.3258x; 1.3258x over previous
#include <cuda_runtime.h>
#include <cuda_bf16.h>
#include <cstdint>

#define N_NODES 50000
#define N_EDGES 800000

// ---------------- scratch (device globals; no runtime allocation) -------------
__device__ float g_deg[N_NODES];
__device__ float g_dinv[N_NODES];
__device__ int   g_count[N_NODES];
__device__ int   g_off[N_NODES + 1];
__device__ int   g_fill[N_NODES];
__device__ int   g_elist[N_EDGES];
__device__ float g_h1[(size_t)N_NODES * 64];
__device__ float g_s[N_NODES];
__device__ float g_sagg[N_NODES];
__device__ float g_v[64];     // gcn2_W @ w_gnn
__device__ float g_u[512];    // fc2_W  @ w_mlp
__device__ float g_cconst;    // fcf_b + fc2_b.w_mlp + gcn2_b.w_gnn
// transposed bf16 hi/lo weights [n][k]
__device__ __nv_bfloat16 g_Bh[512 * 256];
__device__ __nv_bfloat16 g_Bl[512 * 256];
__device__ __nv_bfloat16 g_B1h[64 * 256];
__device__ __nv_bfloat16 g_B1l[64 * 256];

// ---------------- PTX helpers (baseline sm_80+ features only) ------------------
__device__ __forceinline__ uint32_t smem_u32(const void* p) {
    uint32_t a;
    asm("{ .reg .u64 t; cvta.to.shared.u64 t, %1; cvt.u32.u64 %0, t; }" : "=r"(a) : "l"(p));
    return a;
}
#define LDSM4(r0, r1, r2, r3, a) \
    asm volatile("ldmatrix.sync.aligned.m8n8.x4.shared.b16 {%0,%1,%2,%3}, [%4];" \
                 : "=r"(r0), "=r"(r1), "=r"(r2), "=r"(r3) : "r"(a))
#define LDSM2(r0, r1, a) \
    asm volatile("ldmatrix.sync.aligned.m8n8.x2.shared.b16 {%0,%1}, [%2];" \
                 : "=r"(r0), "=r"(r1) : "r"(a))
#define MMA(c, a, b0, b1) \
    asm volatile("mma.sync.aligned.m16n8k16.row.col.f32.bf16.bf16.f32 " \
                 "{%0,%1,%2,%3},{%4,%5,%6,%7},{%8,%9},{%0,%1,%2,%3};" \
                 : "+f"((c)[0]), "+f"((c)[1]), "+f"((c)[2]), "+f"((c)[3]) \
                 : "r"((a)[0]), "r"((a)[1]), "r"((a)[2]), "r"((a)[3]), "r"(b0), "r"(b1))

__device__ __forceinline__ uint32_t pack_bf(__nv_bfloat16 a, __nv_bfloat16 b) {
    __nv_bfloat162 t(a, b);
    return *(uint32_t*)&t;
}
// split float4 into hi/lo bf16 quads packed as uint2 each
__device__ __forceinline__ void split4(float4 v, uint2& hh, uint2& ll) {
    float vv[4] = {v.x, v.y, v.z, v.w};
    __nv_bfloat16 h[4], l[4];
    #pragma unroll
    for (int j = 0; j < 4; j++) {
        h[j] = __float2bfloat16(vv[j]);
        l[j] = __float2bfloat16(vv[j] - __bfloat162float(h[j]));
    }
    hh = make_uint2(pack_bf(h[0], h[1]), pack_bf(h[2], h[3]));
    ll = make_uint2(pack_bf(l[0], l[1]), pack_bf(l[2], l[3]));
}

// ---------------- tiny precompute: collapse trailing GEMMs --------------------
__global__ void precompute_kernel(const float* __restrict__ g2W, const float* __restrict__ g2b,
                                  const float* __restrict__ f2W, const float* __restrict__ f2b,
                                  const float* __restrict__ ffW, const float* __restrict__ ffb) {
    int tid = threadIdx.x;
    if (tid < 512) {
        float acc = 0.f;
        #pragma unroll 8
        for (int c = 0; c < 64; c++) acc += f2W[tid * 64 + c] * ffW[c];
        g_u[tid] = acc;
    }
    if (tid < 64) {
        float acc = 0.f;
        #pragma unroll 8
        for (int c = 0; c < 64; c++) acc += g2W[tid * 64 + c] * ffW[64 + c];
        g_v[tid] = acc;
    }
    if (tid == 0) {
        float acc = ffb[0];
        for (int c = 0; c < 64; c++) acc += f2b[c] * ffW[c] + g2b[c] * ffW[64 + c];
        g_cconst = acc;
    }
}

__global__ void convert_W_kernel(const float* __restrict__ f1W, const float* __restrict__ g1W) {
    int idx = blockIdx.x * blockDim.x + threadIdx.x;
    if (idx < 256 * 512) {
        int k = idx / 512, n = idx % 512;
        float w = f1W[idx];
        __nv_bfloat16 h = __float2bfloat16(w);
        g_Bh[n * 256 + k] = h;
        g_Bl[n * 256 + k] = __float2bfloat16(w - __bfloat162float(h));
    } else if (idx < 256 * 512 + 256 * 64) {
        int i2 = idx - 256 * 512;
        int k = i2 / 64, n = i2 % 64;
        float w = g1W[i2];
        __nv_bfloat16 h = __float2bfloat16(w);
        g_B1h[n * 256 + k] = h;
        g_B1l[n * 256 + k] = __float2bfloat16(w - __bfloat162float(h));
    }
}

// ---------------- graph prep --------------------------------------------------
__global__ void init_kernel() {
    int i = blockIdx.x * blockDim.x + threadIdx.x;
    if (i < N_NODES) { g_deg[i] = 1.0f; g_count[i] = 0; }
}
__global__ void edge_prep_kernel(const int* __restrict__ ei, const float* __restrict__ ea) {
    int e = blockIdx.x * blockDim.x + threadIdx.x;
    if (e < N_EDGES) {
        int dst = ei[N_EDGES + e];
        atomicAdd(&g_deg[dst], ea[e]);
        atomicAdd(&g_count[dst], 1);
    }
}
__global__ void dinv_kernel() {
    int i = blockIdx.x * blockDim.x + threadIdx.x;
    if (i < N_NODES) g_dinv[i] = rsqrtf(g_deg[i]);
}
__global__ void scan_kernel() {
    __shared__ int warp_sums[32];
    int tid = threadIdx.x, lane = tid & 31, wid = tid >> 5;
    int carry = 0;
    for (int base = 0; base < N_NODES; base += 1024) {
        int i = base + tid;
        int v = (i < N_NODES) ? g_count[i] : 0;
        int x = v;
        #pragma unroll
        for (int o = 1; o < 32; o <<= 1) {
            int y = __shfl_up_sync(0xffffffffu, x, o);
            if (lane >= o) x += y;
        }
        if (lane == 31) warp_sums[wid] = x;
        __syncthreads();
        if (wid == 0) {
            int t = warp_sums[lane];
            #pragma unroll
            for (int o = 1; o < 32; o <<= 1) {
                int y = __shfl_up_sync(0xffffffffu, t, o);
                if (lane >= o) t += y;
            }
            warp_sums[lane] = t;
        }
        __syncthreads();
        int warp_prefix = (wid == 0) ? 0 : warp_sums[wid - 1];
        int excl = carry + warp_prefix + x - v;
        if (i < N_NODES) { g_off[i] = excl; g_fill[i] = excl; }
        carry += warp_sums[31];
        __syncthreads();
    }
    if (tid == 0) g_off[N_NODES] = carry;
}
__global__ void fill_kernel(const int* __restrict__ ei) {
    int e = blockIdx.x * blockDim.x + threadIdx.x;
    if (e < N_EDGES) {
        int dst = ei[N_EDGES + e];
        int pos = atomicAdd(&g_fill[dst], 1);
        g_elist[pos] = e;
    }
}

// ---------------- GEMM1 (mma.sync bf16 3-pass): h1 = x @ gcn1_W ---------------
// CTA: M=64, N=64, K=256 resident. 256 thr / 8 warps, warp tile m64 x n8.
// SMEM: Ah 33792 | Al 33792 | Bh 33792 | Bl 33792  (stride 264 bf16 = 528B)
__global__ __launch_bounds__(256) void gemm1_mma_kernel(const float* __restrict__ x) {
    extern __shared__ char smem[];
    const int AH = 0, AL = 33792, BH = 67584, BL = 101376;
    uint32_t sb = smem_u32(smem);
    int tid = threadIdx.x, w = tid >> 5, lane = tid & 31;
    int row0 = blockIdx.x * 64;

    // load A (fp32 -> hi/lo bf16 inline)
    for (int i = tid; i < 64 * 64; i += 256) {
        int r = i >> 6, c4 = i & 63;
        float4 v = make_float4(0.f, 0.f, 0.f, 0.f);
        int row = row0 + r;
        if (row < N_NODES) v = *(const float4*)(x + (size_t)row * 256 + c4 * 4);
        uint2 hh, ll;
        split4(v, hh, ll);
        *(uint2*)(smem + AH + r * 528 + c4 * 8) = hh;
        *(uint2*)(smem + AL + r * 528 + c4 * 8) = ll;
    }
    // load B (already bf16 transposed [n][k])
    for (int i = tid; i < 64 * 32; i += 256) {
        int n = i >> 5, j = i & 31;
        *(uint4*)(smem + BH + n * 528 + j * 16) = *(const uint4*)(g_B1h + n * 256 + j * 8);
        *(uint4*)(smem + BL + n * 528 + j * 16) = *(const uint4*)(g_B1l + n * 256 + j * 8);
    }
    __syncthreads();

    float c[4][4] = {};
    int ll16 = lane & 15;
    #pragma unroll 1
    for (int pass = 0; pass < 3; pass++) {
        uint32_t abase = sb + ((pass == 1) ? AL : AH);
        uint32_t bbase = sb + ((pass == 2) ? BL : BH);
        #pragma unroll 4
        for (int ks = 0; ks < 16; ks++) {
            int kg = ks * 16;
            uint32_t a[4][4];
            #pragma unroll
            for (int mt = 0; mt < 4; mt++)
                LDSM4(a[mt][0], a[mt][1], a[mt][2], a[mt][3],
                      abase + (mt * 16 + ll16) * 528 + kg * 2 + ((lane >> 4) & 1) * 16);
            uint32_t b0, b1;
            LDSM2(b0, b1, bbase + (w * 8 + (ll16 & 7)) * 528 + kg * 2 + ((ll16 >> 3) & 1) * 16);
            #pragma unroll
            for (int mt = 0; mt < 4; mt++) MMA(c[mt], a[mt], b0, b1);
        }
    }
    // write h1 directly from fragments
    int g = lane >> 2, tg = lane & 3;
    int col = w * 8 + tg * 2;
    #pragma unroll
    for (int mt = 0; mt < 4; mt++) {
        #pragma unroll
        for (int h = 0; h < 2; h++) {
            int row = row0 + mt * 16 + h * 8 + g;
            if (row < N_NODES)
                *(float2*)(g_h1 + (size_t)row * 64 + col) = make_float2(c[mt][h * 2], c[mt][h * 2 + 1]);
        }
    }
}

// ---------------- fused: CSR gather + self-loop + bias + relu + dot(v) --------
__global__ void gather1_kernel(const int* __restrict__ ei, const float* __restrict__ ea,
                               const float* __restrict__ b1) {
    int gtid = blockIdx.x * blockDim.x + threadIdx.x;
    int node = gtid >> 5;
    int lane = gtid & 31;
    if (node >= N_NODES) return;
    float dinvi = g_dinv[node];
    float d2 = dinvi * dinvi;
    const float* h1n = g_h1 + (size_t)node * 64;
    float acc0 = h1n[lane] * d2;
    float acc1 = h1n[lane + 32] * d2;
    int beg = g_off[node], end = g_off[node + 1];
    for (int j = beg; j < end; j++) {
        int e = g_elist[j];
        int src = ei[e];
        float norm = ea[e] * g_dinv[src] * dinvi;
        const float* h1s = g_h1 + (size_t)src * 64;
        acc0 += h1s[lane] * norm;
        acc1 += h1s[lane + 32] * norm;
    }
    float gg0 = fmaxf(acc0 + b1[lane], 0.f);
    float gg1 = fmaxf(acc1 + b1[lane + 32], 0.f);
    float p = gg0 * g_v[lane] + gg1 * g_v[lane + 32];
    #pragma unroll
    for (int o = 16; o > 0; o >>= 1) p += __shfl_xor_sync(0xffffffffu, p, o);
    if (lane == 0) { g_s[node] = p; g_sagg[node] = d2 * p; }
}

// ---------------- scalar layer-2 aggregation; writes out = agg + cconst -------
__global__ void gather2_kernel(const int* __restrict__ ei, const float* __restrict__ ea,
                               float* __restrict__ out) {
    int i = blockIdx.x * blockDim.x + threadIdx.x;
    if (i >= N_NODES) return;
    float dinvi = g_dinv[i];
    float acc = g_sagg[i];
    int beg = g_off[i], end = g_off[i + 1];
    for (int j = beg; j < end; j++) {
        int e = g_elist[j];
        int src = ei[e];
        acc += ea[e] * g_dinv[src] * dinvi * g_s[src];
    }
    out[i] = acc + g_cconst;
}

// ---------------- fused MLP (mma.sync bf16 3-pass) ----------------------------
// CTA: M=64, N=256 (gridDim.y=2 halves of 512), K=256. 256 thr / 8 warps,
// warp tile m64 x n32. A full-K resident, B staged in two K=128 chunks.
// SMEM: Ah 33792 | Al 33792 | Bh 69632 | Bl 69632 | b1s 1K | us 1K | sred 2304
__global__ __launch_bounds__(256) void mlp_mma_kernel(const float* __restrict__ uf,
                                                      const float* __restrict__ b1,
                                                      float* __restrict__ out) {
    extern __shared__ char smem[];
    const int AH = 0, AL = 33792, BH = 67584, BL = 137216;
    const int B1S = 206848, US = 207872, SRED = 208896;
    uint32_t sb = smem_u32(smem);
    int tid = threadIdx.x, w = tid >> 5, lane = tid & 31;
    int row0 = blockIdx.x * 64;
    int ngrp = blockIdx.y;            // column half: [ngrp*256, +256)

    float* b1s = (float*)(smem + B1S);
    float* us  = (float*)(smem + US);
    float* sred = (float*)(smem + SRED);
    if (tid < 256) { b1s[tid] = b1[ngrp * 256 + tid]; us[tid] = g_u[ngrp * 256 + tid]; }

    // load A (fp32 -> hi/lo bf16 inline), full K
    for (int i = tid; i < 64 * 64; i += 256) {
        int r = i >> 6, c4 = i & 63;
        float4 v = make_float4(0.f, 0.f, 0.f, 0.f);
        int row = row0 + r;
        if (row < N_NODES) v = *(const float4*)(uf + (size_t)row * 256 + c4 * 4);
        uint2 hh, ll;
        split4(v, hh, ll);
        *(uint2*)(smem + AH + r * 528 + c4 * 8) = hh;
        *(uint2*)(smem + AL + r * 528 + c4 * 8) = ll;
    }

    float c[4][4][4] = {};
    int ll16 = lane & 15;
    int sub = (lane >> 3) & 3;

    #pragma unroll 1
    for (int ch = 0; ch < 2; ch++) {
        __syncthreads();   // protect B buffer across chunks (also covers A load on ch=0)
        // stage B chunk: 256 n-rows x 128 k (stride 136 bf16 = 272B)
        for (int i = tid; i < 256 * 16; i += 256) {
            int n = i >> 4, j = i & 15;
            int kglob = ch * 128 + j * 8;
            const __nv_bfloat16* srcH = g_Bh + (size_t)(ngrp * 256 + n) * 256 + kglob;
            const __nv_bfloat16* srcL = g_Bl + (size_t)(ngrp * 256 + n) * 256 + kglob;
            *(uint4*)(smem + BH + n * 272 + j * 16) = *(const uint4*)srcH;
            *(uint4*)(smem + BL + n * 272 + j * 16) = *(const uint4*)srcL;
        }
        __syncthreads();

        #pragma unroll 1
        for (int pass = 0; pass < 3; pass++) {
            uint32_t abase = sb + ((pass == 1) ? AL : AH);
            uint32_t bbase = sb + ((pass == 2) ? BL : BH);
            #pragma unroll 2
            for (int ks = 0; ks < 8; ks++) {
                int kk = ks * 16;             // local k within chunk
                int kg = ch * 128 + kk;       // global k (A)
                uint32_t a[4][4];
                #pragma unroll
                for (int mt = 0; mt < 4; mt++)
                    LDSM4(a[mt][0], a[mt][1], a[mt][2], a[mt][3],
                          abase + (mt * 16 + ll16) * 528 + kg * 2 + ((lane >> 4) & 1) * 16);
                uint32_t b[4][2];
                #pragma unroll
                for (int ntp = 0; ntp < 2; ntp++) {
                    int noff = w * 32 + ntp * 16 + ((sub & 2) ? 8 : 0) + (lane & 7);
                    uint32_t r0, r1, r2, r3;
                    LDSM4(r0, r1, r2, r3, bbase + noff * 272 + kk * 2 + (sub & 1) * 16);
                    b[ntp * 2][0] = r0; b[ntp * 2][1] = r1;
                    b[ntp * 2 + 1][0] = r2; b[ntp * 2 + 1][1] = r3;
                }
                #pragma unroll
                for (int mt = 0; mt < 4; mt++)
                    #pragma unroll
                    for (int nt = 0; nt < 4; nt++)
                        MMA(c[mt][nt], a[mt], b[nt][0], b[nt][1]);
            }
        }
    }

    // epilogue: bias + relu + dot(u) fused; reduce quad -> smem -> atomicAdd
    int g = lane >> 2, tg = lane & 3;
    #pragma unroll
    for (int mt = 0; mt < 4; mt++) {
        float rs[2] = {0.f, 0.f};
        #pragma unroll
        for (int nt = 0; nt < 4; nt++) {
            int col = w * 32 + nt * 8 + tg * 2;
            float bb0 = b1s[col], uu0 = us[col];
            float bb1 = b1s[col + 1], uu1 = us[col + 1];
            #pragma unroll
            for (int h = 0; h < 2; h++) {
                float h0 = c[mt][nt][h * 2] + bb0;
                float h1 = c[mt][nt][h * 2 + 1] + bb1;
                if (h0 > 0.f) rs[h] += h0 * uu0;
                if (h1 > 0.f) rs[h] += h1 * uu1;
            }
        }
        #pragma unroll
        for (int h = 0; h < 2; h++) {
            rs[h] += __shfl_xor_sync(0xffffffffu, rs[h], 1);
            rs[h] += __shfl_xor_sync(0xffffffffu, rs[h], 2);
            if (tg == 0) sred[(mt * 16 + h * 8 + g) * 9 + w] = rs[h];
        }
    }
    __syncthreads();
    if (tid < 64) {
        float sum = 0.f;
        #pragma unroll
        for (int t = 0; t < 8; t++) sum += sred[tid * 9 + t];
        int row = row0 + tid;
        if (row < N_NODES) atomicAdd(out + row, sum);
    }
}

// ------------------------------------------------------------------------------
extern "C" void kernel_launch(void* const* d_in, const int* in_sizes, int n_in,
                              void* d_out, int out_size) {
    const float* x   = (const float*)d_in[0];
    const int*   ei  = (const int*)d_in[1];
    const float* ea  = (const float*)d_in[2];
    const float* uf  = (const float*)d_in[3];
    const float* g1W = (const float*)d_in[4];
    const float* g1b = (const float*)d_in[5];
    const float* g2W = (const float*)d_in[6];
    const float* g2b = (const float*)d_in[7];
    const float* f1W = (const float*)d_in[8];
    const float* f1b = (const float*)d_in[9];
    const float* f2W = (const float*)d_in[10];
    const float* f2b = (const float*)d_in[11];
    const float* ffW = (const float*)d_in[12];
    const float* ffb = (const float*)d_in[13];
    float* out = (float*)d_out;

    cudaFuncSetAttribute(gemm1_mma_kernel, cudaFuncAttributeMaxDynamicSharedMemorySize, 135168);
    cudaFuncSetAttribute(mlp_mma_kernel, cudaFuncAttributeMaxDynamicSharedMemorySize, 211200);

    precompute_kernel<<<1, 512>>>(g2W, g2b, f2W, f2b, ffW, ffb);
    convert_W_kernel<<<(256 * 512 + 256 * 64 + 255) / 256, 256>>>(f1W, g1W);
    init_kernel<<<(N_NODES + 255) / 256, 256>>>();
    edge_prep_kernel<<<(N_EDGES + 255) / 256, 256>>>(ei, ea);
    dinv_kernel<<<(N_NODES + 255) / 256, 256>>>();
    scan_kernel<<<1, 1024>>>();
    fill_kernel<<<(N_EDGES + 255) / 256, 256>>>(ei);
    gemm1_mma_kernel<<<(N_NODES + 63) / 64, 256, 135168>>>(x);
    gather1_kernel<<<((size_t)N_NODES * 32 + 255) / 256, 256>>>(ei, ea, g1b);
    gather2_kernel<<<(N_NODES + 255) / 256, 256>>>(ei, ea, out);
    mlp_mma_kernel<<<dim3((N_NODES + 63) / 64, 2), 256, 211200>>>(uf, f1b, out);
}

// round 8
// speedup vs baseline: 1.6495x; 1.2441x over previous
#include <cuda_runtime.h>
#include <cuda_bf16.h>
#include <cstdint>

#define N_NODES 50000
#define N_EDGES 800000

// ---------------- scratch (device globals; no runtime allocation) -------------
__device__ float g_deg[N_NODES];
__device__ float g_dinv[N_NODES];
__device__ int   g_count[N_NODES];
__device__ int   g_off[N_NODES + 1];
__device__ int   g_fill[N_NODES];
__device__ int   g_elist[N_EDGES];
__device__ float g_h1[(size_t)N_NODES * 64];
__device__ float g_s[N_NODES];
__device__ float g_sagg[N_NODES];
__device__ float g_v[64];     // gcn2_W @ w_gnn
__device__ float g_u[512];    // fc2_W  @ w_mlp
__device__ float g_cconst;    // fcf_b + fc2_b.w_mlp + gcn2_b.w_gnn
__device__ float g_mlp[2][N_NODES];                    // per-N-half MLP partials
// bf16 hi/lo operands
__device__ __nv_bfloat16 g_Ah[(size_t)N_NODES * 256];  // uf hi
__device__ __nv_bfloat16 g_Al[(size_t)N_NODES * 256];  // uf lo
__device__ __nv_bfloat16 g_Bh[512 * 256];              // fc1_W^T hi  [n][k]
__device__ __nv_bfloat16 g_Bl[512 * 256];              // fc1_W^T lo
__device__ __nv_bfloat16 g_B1h[64 * 256];              // gcn1_W^T hi
__device__ __nv_bfloat16 g_B1l[64 * 256];              // gcn1_W^T lo

// ---------------- PTX helpers (baseline sm_80+ features only) ------------------
__device__ __forceinline__ uint32_t smem_u32(const void* p) {
    uint32_t a;
    asm("{ .reg .u64 t; cvta.to.shared.u64 t, %1; cvt.u32.u64 %0, t; }" : "=r"(a) : "l"(p));
    return a;
}
#define LDSM4(r0, r1, r2, r3, a) \
    asm volatile("ldmatrix.sync.aligned.m8n8.x4.shared.b16 {%0,%1,%2,%3}, [%4];" \
                 : "=r"(r0), "=r"(r1), "=r"(r2), "=r"(r3) : "r"(a))
#define LDSM2(r0, r1, a) \
    asm volatile("ldmatrix.sync.aligned.m8n8.x2.shared.b16 {%0,%1}, [%2];" \
                 : "=r"(r0), "=r"(r1) : "r"(a))
#define MMA(c, a, b0, b1) \
    asm volatile("mma.sync.aligned.m16n8k16.row.col.f32.bf16.bf16.f32 " \
                 "{%0,%1,%2,%3},{%4,%5,%6,%7},{%8,%9},{%0,%1,%2,%3};" \
                 : "+f"((c)[0]), "+f"((c)[1]), "+f"((c)[2]), "+f"((c)[3]) \
                 : "r"((a)[0]), "r"((a)[1]), "r"((a)[2]), "r"((a)[3]), "r"(b0), "r"(b1))

__device__ __forceinline__ uint32_t pack_bf(__nv_bfloat16 a, __nv_bfloat16 b) {
    __nv_bfloat162 t(a, b);
    return *(uint32_t*)&t;
}
__device__ __forceinline__ void split4(float4 v, uint2& hh, uint2& ll) {
    float vv[4] = {v.x, v.y, v.z, v.w};
    __nv_bfloat16 h[4], l[4];
    #pragma unroll
    for (int j = 0; j < 4; j++) {
        h[j] = __float2bfloat16(vv[j]);
        l[j] = __float2bfloat16(vv[j] - __bfloat162float(h[j]));
    }
    hh = make_uint2(pack_bf(h[0], h[1]), pack_bf(h[2], h[3]));
    ll = make_uint2(pack_bf(l[0], l[1]), pack_bf(l[2], l[3]));
}

// ---------------- tiny precompute: collapse trailing GEMMs --------------------
__global__ void precompute_kernel(const float* __restrict__ g2W, const float* __restrict__ g2b,
                                  const float* __restrict__ f2W, const float* __restrict__ f2b,
                                  const float* __restrict__ ffW, const float* __restrict__ ffb) {
    int tid = threadIdx.x;
    if (tid < 512) {
        float acc = 0.f;
        #pragma unroll 8
        for (int c = 0; c < 64; c++) acc += f2W[tid * 64 + c] * ffW[c];
        g_u[tid] = acc;
    }
    if (tid < 64) {
        float acc = 0.f;
        #pragma unroll 8
        for (int c = 0; c < 64; c++) acc += g2W[tid * 64 + c] * ffW[64 + c];
        g_v[tid] = acc;
    }
    if (tid == 0) {
        float acc = ffb[0];
        for (int c = 0; c < 64; c++) acc += f2b[c] * ffW[c] + g2b[c] * ffW[64 + c];
        g_cconst = acc;
    }
}

__global__ void convert_W_kernel(const float* __restrict__ f1W, const float* __restrict__ g1W) {
    int idx = blockIdx.x * blockDim.x + threadIdx.x;
    if (idx < 256 * 512) {
        int k = idx / 512, n = idx % 512;
        float w = f1W[idx];
        __nv_bfloat16 h = __float2bfloat16(w);
        g_Bh[n * 256 + k] = h;
        g_Bl[n * 256 + k] = __float2bfloat16(w - __bfloat162float(h));
    } else if (idx < 256 * 512 + 256 * 64) {
        int i2 = idx - 256 * 512;
        int k = i2 / 64, n = i2 % 64;
        float w = g1W[i2];
        __nv_bfloat16 h = __float2bfloat16(w);
        g_B1h[n * 256 + k] = h;
        g_B1l[n * 256 + k] = __float2bfloat16(w - __bfloat162float(h));
    }
}

__global__ void convertA_kernel(const float* __restrict__ uf) {
    int i = blockIdx.x * blockDim.x + threadIdx.x;   // float4 index
    if (i < N_NODES * 64) {
        uint2 hh, ll;
        split4(((const float4*)uf)[i], hh, ll);
        *(uint2*)(g_Ah + (size_t)i * 4) = hh;
        *(uint2*)(g_Al + (size_t)i * 4) = ll;
    }
}

// ---------------- graph prep --------------------------------------------------
__global__ void init_kernel() {
    int i = blockIdx.x * blockDim.x + threadIdx.x;
    if (i < N_NODES) { g_deg[i] = 1.0f; g_count[i] = 0; }
}
__global__ void edge_prep_kernel(const int* __restrict__ ei, const float* __restrict__ ea) {
    int e = blockIdx.x * blockDim.x + threadIdx.x;
    if (e < N_EDGES) {
        int dst = ei[N_EDGES + e];
        atomicAdd(&g_deg[dst], ea[e]);
        atomicAdd(&g_count[dst], 1);
    }
}
__global__ void dinv_kernel() {
    int i = blockIdx.x * blockDim.x + threadIdx.x;
    if (i < N_NODES) g_dinv[i] = rsqrtf(g_deg[i]);
}
__global__ void scan_kernel() {
    __shared__ int warp_sums[32];
    int tid = threadIdx.x, lane = tid & 31, wid = tid >> 5;
    int carry = 0;
    for (int base = 0; base < N_NODES; base += 1024) {
        int i = base + tid;
        int v = (i < N_NODES) ? g_count[i] : 0;
        int x = v;
        #pragma unroll
        for (int o = 1; o < 32; o <<= 1) {
            int y = __shfl_up_sync(0xffffffffu, x, o);
            if (lane >= o) x += y;
        }
        if (lane == 31) warp_sums[wid] = x;
        __syncthreads();
        if (wid == 0) {
            int t = warp_sums[lane];
            #pragma unroll
            for (int o = 1; o < 32; o <<= 1) {
                int y = __shfl_up_sync(0xffffffffu, t, o);
                if (lane >= o) t += y;
            }
            warp_sums[lane] = t;
        }
        __syncthreads();
        int warp_prefix = (wid == 0) ? 0 : warp_sums[wid - 1];
        int excl = carry + warp_prefix + x - v;
        if (i < N_NODES) { g_off[i] = excl; g_fill[i] = excl; }
        carry += warp_sums[31];
        __syncthreads();
    }
    if (tid == 0) g_off[N_NODES] = carry;
}
__global__ void fill_kernel(const int* __restrict__ ei) {
    int e = blockIdx.x * blockDim.x + threadIdx.x;
    if (e < N_EDGES) {
        int dst = ei[N_EDGES + e];
        int pos = atomicAdd(&g_fill[dst], 1);
        g_elist[pos] = e;
    }
}

// ---------------- GEMM1 (mma.sync bf16 3-pass): h1 = x @ gcn1_W ---------------
// CTA: M=64, N=64, K=256 resident. 256 thr / 8 warps, warp tile m64 x n8.
__global__ __launch_bounds__(256) void gemm1_mma_kernel(const float* __restrict__ x) {
    extern __shared__ char smem[];
    const int AH = 0, AL = 33792, BH = 67584, BL = 101376;
    uint32_t sb = smem_u32(smem);
    int tid = threadIdx.x, w = tid >> 5, lane = tid & 31;
    int row0 = blockIdx.x * 64;

    for (int i = tid; i < 64 * 64; i += 256) {
        int r = i >> 6, c4 = i & 63;
        float4 v = make_float4(0.f, 0.f, 0.f, 0.f);
        int row = row0 + r;
        if (row < N_NODES) v = *(const float4*)(x + (size_t)row * 256 + c4 * 4);
        uint2 hh, ll;
        split4(v, hh, ll);
        *(uint2*)(smem + AH + r * 528 + c4 * 8) = hh;
        *(uint2*)(smem + AL + r * 528 + c4 * 8) = ll;
    }
    for (int i = tid; i < 64 * 32; i += 256) {
        int n = i >> 5, j = i & 31;
        *(uint4*)(smem + BH + n * 528 + j * 16) = *(const uint4*)(g_B1h + n * 256 + j * 8);
        *(uint4*)(smem + BL + n * 528 + j * 16) = *(const uint4*)(g_B1l + n * 256 + j * 8);
    }
    __syncthreads();

    float c[4][4] = {};
    int ll16 = lane & 15;
    #pragma unroll 2
    for (int ks = 0; ks < 16; ks++) {
        int kg = ks * 16;
        uint32_t ah[4][4], al[4][4];
        #pragma unroll
        for (int mt = 0; mt < 4; mt++) {
            uint32_t off = (mt * 16 + ll16) * 528 + kg * 2 + ((lane >> 4) & 1) * 16;
            LDSM4(ah[mt][0], ah[mt][1], ah[mt][2], ah[mt][3], sb + AH + off);
            LDSM4(al[mt][0], al[mt][1], al[mt][2], al[mt][3], sb + AL + off);
        }
        uint32_t boff = (w * 8 + (ll16 & 7)) * 528 + kg * 2 + ((ll16 >> 3) & 1) * 16;
        uint32_t bh0, bh1, bl0, bl1;
        LDSM2(bh0, bh1, sb + BH + boff);
        LDSM2(bl0, bl1, sb + BL + boff);
        #pragma unroll
        for (int mt = 0; mt < 4; mt++) {
            MMA(c[mt], ah[mt], bh0, bh1);
            MMA(c[mt], al[mt], bh0, bh1);
            MMA(c[mt], ah[mt], bl0, bl1);
        }
    }
    int g = lane >> 2, tg = lane & 3;
    int col = w * 8 + tg * 2;
    #pragma unroll
    for (int mt = 0; mt < 4; mt++) {
        #pragma unroll
        for (int h = 0; h < 2; h++) {
            int row = row0 + mt * 16 + h * 8 + g;
            if (row < N_NODES)
                *(float2*)(g_h1 + (size_t)row * 64 + col) = make_float2(c[mt][h * 2], c[mt][h * 2 + 1]);
        }
    }
}

// ---------------- fused: CSR gather + self-loop + bias + relu + dot(v) --------
__global__ void gather1_kernel(const int* __restrict__ ei, const float* __restrict__ ea,
                               const float* __restrict__ b1) {
    int gtid = blockIdx.x * blockDim.x + threadIdx.x;
    int node = gtid >> 5;
    int lane = gtid & 31;
    if (node >= N_NODES) return;
    float dinvi = g_dinv[node];
    float d2 = dinvi * dinvi;
    const float* h1n = g_h1 + (size_t)node * 64;
    float acc0 = h1n[lane] * d2;
    float acc1 = h1n[lane + 32] * d2;
    int beg = g_off[node], end = g_off[node + 1];
    for (int j = beg; j < end; j++) {
        int e = g_elist[j];
        int src = ei[e];
        float norm = ea[e] * g_dinv[src] * dinvi;
        const float* h1s = g_h1 + (size_t)src * 64;
        acc0 += h1s[lane] * norm;
        acc1 += h1s[lane + 32] * norm;
    }
    float gg0 = fmaxf(acc0 + b1[lane], 0.f);
    float gg1 = fmaxf(acc1 + b1[lane + 32], 0.f);
    float p = gg0 * g_v[lane] + gg1 * g_v[lane + 32];
    #pragma unroll
    for (int o = 16; o > 0; o >>= 1) p += __shfl_xor_sync(0xffffffffu, p, o);
    if (lane == 0) { g_s[node] = p; g_sagg[node] = d2 * p; }
}

// ---------------- scalar layer-2 aggregation ----------------------------------
__global__ void gather2_kernel(const int* __restrict__ ei, const float* __restrict__ ea) {
    int i = blockIdx.x * blockDim.x + threadIdx.x;
    if (i >= N_NODES) return;
    float dinvi = g_dinv[i];
    float acc = g_sagg[i];
    int beg = g_off[i], end = g_off[i + 1];
    for (int j = beg; j < end; j++) {
        int e = g_elist[j];
        int src = ei[e];
        acc += ea[e] * g_dinv[src] * dinvi * g_s[src];
    }
    g_sagg[i] = acc;
}

// ---------------- fused MLP (mma.sync bf16, pass-fused, 2 CTA/SM) -------------
// CTA: M=32, N=256 (blockIdx.y half of 512), K chunks of 64. 256 thr / 8 warps,
// warp tile m32 x n32. SMEM: Ah 16896 | Al 16896 | Bh 36864 | Bl 36864 |
// b1s 1K | us 1K | sred 1152  = 110720 B -> 2 CTAs/SM.
__global__ __launch_bounds__(256, 2) void mlp_mma_kernel(const float* __restrict__ b1) {
    extern __shared__ char smem[];
    const int AH = 0, AL = 16896, BH = 33792, BL = 70656;
    const int B1S = 107520, US = 108544, SRED = 109568;
    uint32_t sb = smem_u32(smem);
    int tid = threadIdx.x, w = tid >> 5, lane = tid & 31;
    int row0 = blockIdx.x * 32;
    int ngrp = blockIdx.y;

    float* b1s = (float*)(smem + B1S);
    float* us  = (float*)(smem + US);
    float* sred = (float*)(smem + SRED);
    if (tid < 256) { b1s[tid] = b1[ngrp * 256 + tid]; us[tid] = g_u[ngrp * 256 + tid]; }

    // stage A (pre-split bf16 hi/lo), full K=256: 32 rows x 512B
    for (int i = tid; i < 1024; i += 256) {
        int r = i >> 5, c = i & 31;
        int row = row0 + r;
        uint4 vh = make_uint4(0, 0, 0, 0), vl = vh;
        if (row < N_NODES) {
            vh = *(const uint4*)(g_Ah + (size_t)row * 256 + c * 8);
            vl = *(const uint4*)(g_Al + (size_t)row * 256 + c * 8);
        }
        *(uint4*)(smem + AH + r * 528 + c * 16) = vh;
        *(uint4*)(smem + AL + r * 528 + c * 16) = vl;
    }

    float c[2][4][4] = {};
    int ll16 = lane & 15;
    int sub = (lane >> 3) & 3;

    #pragma unroll 1
    for (int ch = 0; ch < 4; ch++) {
        __syncthreads();
        // stage B chunk: 256 n-rows x 64 k (stride 144B)
        for (int i = tid; i < 2048; i += 256) {
            int n = i >> 3, j = i & 7;
            int kglob = ch * 64 + j * 8;
            *(uint4*)(smem + BH + n * 144 + j * 16) =
                *(const uint4*)(g_Bh + (size_t)(ngrp * 256 + n) * 256 + kglob);
            *(uint4*)(smem + BL + n * 144 + j * 16) =
                *(const uint4*)(g_Bl + (size_t)(ngrp * 256 + n) * 256 + kglob);
        }
        __syncthreads();

        #pragma unroll
        for (int ks = 0; ks < 4; ks++) {
            int kk = ks * 16;
            int kg = ch * 64 + kk;
            uint32_t ah[2][4], al[2][4];
            #pragma unroll
            for (int mt = 0; mt < 2; mt++) {
                uint32_t off = (mt * 16 + ll16) * 528 + kg * 2 + ((lane >> 4) & 1) * 16;
                LDSM4(ah[mt][0], ah[mt][1], ah[mt][2], ah[mt][3], sb + AH + off);
                LDSM4(al[mt][0], al[mt][1], al[mt][2], al[mt][3], sb + AL + off);
            }
            uint32_t bh[4][2], bl[4][2];
            #pragma unroll
            for (int ntp = 0; ntp < 2; ntp++) {
                int noff = w * 32 + ntp * 16 + ((sub & 2) ? 8 : 0) + (lane & 7);
                uint32_t boff = noff * 144 + kk * 2 + (sub & 1) * 16;
                uint32_t r0, r1, r2, r3;
                LDSM4(r0, r1, r2, r3, sb + BH + boff);
                bh[ntp * 2][0] = r0; bh[ntp * 2][1] = r1;
                bh[ntp * 2 + 1][0] = r2; bh[ntp * 2 + 1][1] = r3;
                LDSM4(r0, r1, r2, r3, sb + BL + boff);
                bl[ntp * 2][0] = r0; bl[ntp * 2][1] = r1;
                bl[ntp * 2 + 1][0] = r2; bl[ntp * 2 + 1][1] = r3;
            }
            #pragma unroll
            for (int mt = 0; mt < 2; mt++)
                #pragma unroll
                for (int nt = 0; nt < 4; nt++) {
                    MMA(c[mt][nt], ah[mt], bh[nt][0], bh[nt][1]);
                    MMA(c[mt][nt], al[mt], bh[nt][0], bh[nt][1]);
                    MMA(c[mt][nt], ah[mt], bl[nt][0], bl[nt][1]);
                }
        }
    }

    // epilogue: bias + relu + dot(u); quad-shuffle -> smem -> per-half write
    int g = lane >> 2, tg = lane & 3;
    #pragma unroll
    for (int mt = 0; mt < 2; mt++) {
        float rs[2] = {0.f, 0.f};
        #pragma unroll
        for (int nt = 0; nt < 4; nt++) {
            int col = w * 32 + nt * 8 + tg * 2;
            float bb0 = b1s[col], uu0 = us[col];
            float bb1 = b1s[col + 1], uu1 = us[col + 1];
            #pragma unroll
            for (int h = 0; h < 2; h++) {
                float h0 = c[mt][nt][h * 2] + bb0;
                float h1 = c[mt][nt][h * 2 + 1] + bb1;
                if (h0 > 0.f) rs[h] += h0 * uu0;
                if (h1 > 0.f) rs[h] += h1 * uu1;
            }
        }
        #pragma unroll
        for (int h = 0; h < 2; h++) {
            rs[h] += __shfl_xor_sync(0xffffffffu, rs[h], 1);
            rs[h] += __shfl_xor_sync(0xffffffffu, rs[h], 2);
            if (tg == 0) sred[(mt * 16 + h * 8 + g) * 9 + w] = rs[h];
        }
    }
    __syncthreads();
    if (tid < 32) {
        float sum = 0.f;
        #pragma unroll
        for (int t = 0; t < 8; t++) sum += sred[tid * 9 + t];
        int row = row0 + tid;
        if (row < N_NODES) g_mlp[ngrp][row] = sum;
    }
}

// ---------------- final combine -----------------------------------------------
__global__ void final_kernel(float* __restrict__ out) {
    int i = blockIdx.x * blockDim.x + threadIdx.x;
    if (i < N_NODES)
        out[i] = g_mlp[0][i] + g_mlp[1][i] + g_sagg[i] + g_cconst;
}

// ------------------------------------------------------------------------------
extern "C" void kernel_launch(void* const* d_in, const int* in_sizes, int n_in,
                              void* d_out, int out_size) {
    const float* x   = (const float*)d_in[0];
    const int*   ei  = (const int*)d_in[1];
    const float* ea  = (const float*)d_in[2];
    const float* uf  = (const float*)d_in[3];
    const float* g1W = (const float*)d_in[4];
    const float* g1b = (const float*)d_in[5];
    const float* g2W = (const float*)d_in[6];
    const float* g2b = (const float*)d_in[7];
    const float* f1W = (const float*)d_in[8];
    const float* f1b = (const float*)d_in[9];
    const float* f2W = (const float*)d_in[10];
    const float* f2b = (const float*)d_in[11];
    const float* ffW = (const float*)d_in[12];
    const float* ffb = (const float*)d_in[13];
    float* out = (float*)d_out;

    // one-time infra (created on the uncaptured correctness call, reused under capture)
    static cudaStream_t s1 = nullptr;
    static cudaEvent_t ev0, evG, ev1;
    if (!s1) {
        cudaStreamCreateWithFlags(&s1, cudaStreamNonBlocking);
        cudaEventCreateWithFlags(&ev0, cudaEventDisableTiming);
        cudaEventCreateWithFlags(&evG, cudaEventDisableTiming);
        cudaEventCreateWithFlags(&ev1, cudaEventDisableTiming);
        cudaFuncSetAttribute(gemm1_mma_kernel, cudaFuncAttributeMaxDynamicSharedMemorySize, 135168);
        cudaFuncSetAttribute(mlp_mma_kernel, cudaFuncAttributeMaxDynamicSharedMemorySize, 110720);
    }

    // fork: graph-prep branch on s1
    cudaEventRecord(ev0, 0);
    cudaStreamWaitEvent(s1, ev0, 0);
    init_kernel<<<(N_NODES + 255) / 256, 256, 0, s1>>>();
    edge_prep_kernel<<<(N_EDGES + 255) / 256, 256, 0, s1>>>(ei, ea);
    dinv_kernel<<<(N_NODES + 255) / 256, 256, 0, s1>>>();
    scan_kernel<<<1, 1024, 0, s1>>>();
    fill_kernel<<<(N_EDGES + 255) / 256, 256, 0, s1>>>(ei);

    // main branch: converts + GEMMs
    precompute_kernel<<<1, 512>>>(g2W, g2b, f2W, f2b, ffW, ffb);
    convert_W_kernel<<<(256 * 512 + 256 * 64 + 255) / 256, 256>>>(f1W, g1W);
    convertA_kernel<<<(N_NODES * 64 + 255) / 256, 256>>>(uf);
    gemm1_mma_kernel<<<(N_NODES + 63) / 64, 256, 135168>>>(x);
    cudaEventRecord(evG, 0);

    // s1 continues: gathers need gemm1 (h1) + precompute (g_v)
    cudaStreamWaitEvent(s1, evG, 0);
    gather1_kernel<<<((size_t)N_NODES * 32 + 255) / 256, 256, 0, s1>>>(ei, ea, g1b);
    gather2_kernel<<<(N_NODES + 255) / 256, 256, 0, s1>>>(ei, ea);
    cudaEventRecord(ev1, s1);

    // main branch: big MLP GEMM overlaps the whole graph branch
    mlp_mma_kernel<<<dim3((N_NODES + 31) / 32, 2), 256, 110720>>>(f1b);

    // join + combine
    cudaStreamWaitEvent(0, ev1, 0);
    final_kernel<<<(N_NODES + 255) / 256, 256>>>(out);
}